// round 16
// baseline (speedup 1.0000x reference)
#include <cuda_runtime.h>
#include <cuda_fp16.h>
#include <cstdint>

#define T_TOK 4096
#define HID   1024
#define INTER 4096
#define NEXP  8

typedef unsigned short u16;
typedef unsigned int   u32;
typedef unsigned long long u64;

// ---------------------------------------------------------------------------
// Device scratch (fp16 operands)
// ---------------------------------------------------------------------------
__device__ u16 g_xh[(size_t)T_TOK * HID];            // fp16 x [T][H]
__device__ u16 g_w1h[(size_t)NEXP * HID * INTER];    // [E][I][H] transposed fp16
__device__ u16 g_w2h[(size_t)NEXP * HID * INTER];    // [E][H][I] transposed fp16
__device__ u16 g_hh[(size_t)NEXP * T_TOK * INTER];   // per-expert h fp16
__device__ u16 g_yh[(size_t)NEXP * T_TOK * HID];     // per-expert gate-weighted y fp16
__device__ float g_gate[T_TOK * NEXP];

// ---------------------------------------------------------------------------
// Helpers
// ---------------------------------------------------------------------------
__device__ __forceinline__ u32 smem_u32(const void* p) {
    u32 a;
    asm("{ .reg .u64 t; cvta.to.shared.u64 t, %1; cvt.u32.u64 %0, t; }"
        : "=r"(a) : "l"(p));
    return a;
}
__device__ __forceinline__ void cp16(u32 dst, const void* src) {
    asm volatile("cp.async.cg.shared.global [%0], [%1], 16;"
                 :: "r"(dst), "l"(src));
}
__device__ __forceinline__ void ldm_x4(u32& r0, u32& r1, u32& r2, u32& r3, u32 a) {
    asm volatile("ldmatrix.sync.aligned.m8n8.x4.shared.b16 {%0,%1,%2,%3}, [%4];"
                 : "=r"(r0), "=r"(r1), "=r"(r2), "=r"(r3) : "r"(a));
}
__device__ __forceinline__ void mma_f16(float* c, const u32* a, const u32* b) {
    asm volatile("mma.sync.aligned.m16n8k16.row.col.f32.f16.f16.f32 "
                 "{%0,%1,%2,%3}, {%4,%5,%6,%7}, {%8,%9}, {%0,%1,%2,%3};"
                 : "+f"(c[0]), "+f"(c[1]), "+f"(c[2]), "+f"(c[3])
                 : "r"(a[0]), "r"(a[1]), "r"(a[2]), "r"(a[3]),
                   "r"(b[0]), "r"(b[1]));
}
__device__ __forceinline__ float gelu_exact(float v) { return v * normcdff(v); }

// ---------------------------------------------------------------------------
// Gate: logits = x @ Wg^T, softmax over E=8. One warp per token.
// ---------------------------------------------------------------------------
__global__ void gate_kernel(const float* __restrict__ x,
                            const float* __restrict__ Wg,
                            float* __restrict__ gate) {
    int warp = (blockIdx.x * blockDim.x + threadIdx.x) >> 5;
    int lane = threadIdx.x & 31;
    if (warp >= T_TOK) return;
    const float* xr = x + (size_t)warp * HID;
    float acc[NEXP];
#pragma unroll
    for (int e = 0; e < NEXP; e++) acc[e] = 0.f;
    for (int k = lane; k < HID; k += 32) {
        float xv = xr[k];
#pragma unroll
        for (int e = 0; e < NEXP; e++) acc[e] = fmaf(xv, Wg[e * HID + k], acc[e]);
    }
#pragma unroll
    for (int e = 0; e < NEXP; e++)
#pragma unroll
        for (int off = 16; off > 0; off >>= 1)
            acc[e] += __shfl_xor_sync(0xffffffffu, acc[e], off);
    if (lane == 0) {
        float mx = acc[0];
#pragma unroll
        for (int e = 1; e < NEXP; e++) mx = fmaxf(mx, acc[e]);
        float s = 0.f;
#pragma unroll
        for (int e = 0; e < NEXP; e++) { acc[e] = expf(acc[e] - mx); s += acc[e]; }
        float inv = 1.f / s;
#pragma unroll
        for (int e = 0; e < NEXP; e++) gate[warp * NEXP + e] = acc[e] * inv;
    }
}

// ---------------------------------------------------------------------------
// x fp32 -> fp16, layout preserved
// ---------------------------------------------------------------------------
__global__ void xcvt_kernel(const float* __restrict__ in, u16* __restrict__ out,
                            size_t n4) {
    size_t i = (size_t)blockIdx.x * blockDim.x + threadIdx.x;
    if (i >= n4) return;
    float4 v = reinterpret_cast<const float4*>(in)[i];
    __half h[4];
    h[0] = __float2half_rn(v.x); h[1] = __float2half_rn(v.y);
    h[2] = __float2half_rn(v.z); h[3] = __float2half_rn(v.w);
    reinterpret_cast<u64*>(out)[i] = *reinterpret_cast<u64*>(h);
}

// ---------------------------------------------------------------------------
// Both W1 [E][1024][4096] and W2 [E][4096][1024] -> transposed fp16, one grid.
// ---------------------------------------------------------------------------
__global__ void tcvt2_kernel(const float* __restrict__ W1,
                             const float* __restrict__ W2,
                             u16* __restrict__ o1, u16* __restrict__ o2) {
    __shared__ float t[64][33];
    int b = blockIdx.x;
    const float* Win; u16* oT; int R, C, c0, r0;
    if (b < 16384) {                 // W1: R=1024, C=4096; 128 x 16 tiles/expert
        int e = b >> 11, tt = b & 2047;
        R = HID; C = INTER;
        c0 = (tt & 127) * 32; r0 = (tt >> 7) * 64;
        Win = W1 + (size_t)e * R * C;
        oT  = o1 + (size_t)e * R * C;
    } else {                          // W2: R=4096, C=1024; 32 x 64 tiles/expert
        b -= 16384;
        int e = b >> 11, tt = b & 2047;
        R = INTER; C = HID;
        c0 = (tt & 31) * 32; r0 = (tt >> 5) * 64;
        Win = W2 + (size_t)e * R * C;
        oT  = o2 + (size_t)e * R * C;
    }
    int tx = threadIdx.x, ty = threadIdx.y;  // (32, 8)
#pragma unroll
    for (int i = 0; i < 8; i++)
        t[ty + i * 8][tx] = Win[(size_t)(r0 + ty + i * 8) * C + c0 + tx];
    __syncthreads();
#pragma unroll
    for (int i = 0; i < 4; i++) {
        int crow = ty + i * 8;
        __half h0 = __float2half_rn(t[2 * tx + 0][crow]);
        __half h1 = __float2half_rn(t[2 * tx + 1][crow]);
        size_t off = (size_t)(c0 + crow) * R + r0 + 2 * tx;
        *reinterpret_cast<u32*>(oT + off) =
            (u32)__half_as_ushort(h0) | ((u32)__half_as_ushort(h1) << 16);
    }
}

// ---------------------------------------------------------------------------
// Final reduce: out[t,h] = sum_e yh[e,t,h]  (gate already folded in)
// ---------------------------------------------------------------------------
__global__ void reduce_kernel(const u16* __restrict__ yh,
                              float* __restrict__ out) {
    size_t idx = (size_t)blockIdx.x * blockDim.x + threadIdx.x;  // over T*H/8
    if (idx >= (size_t)T_TOK * HID / 8) return;
    float s[8] = {0.f, 0.f, 0.f, 0.f, 0.f, 0.f, 0.f, 0.f};
#pragma unroll
    for (int e = 0; e < NEXP; e++) {
        uint4 v = reinterpret_cast<const uint4*>(
            yh + (size_t)e * T_TOK * HID)[idx];
        const u32 w[4] = {v.x, v.y, v.z, v.w};
#pragma unroll
        for (int q = 0; q < 4; q++) {
            float2 f = __half22float2(*reinterpret_cast<const __half2*>(&w[q]));
            s[q * 2 + 0] += f.x;
            s[q * 2 + 1] += f.y;
        }
    }
#pragma unroll
    for (int q = 0; q < 2; q++) {
        float4 o = make_float4(s[q * 4 + 0], s[q * 4 + 1],
                               s[q * 4 + 2], s[q * 4 + 3]);
        reinterpret_cast<float4*>(out)[idx * 2 + q] = o;
    }
}

// ---------------------------------------------------------------------------
// FP16 mma.sync GEMM over grid.z experts: C = A[M,K] @ B[N,K]^T (fp32 accum)
// 128x128 CTA tile, BK=64 halves, 256 threads (8 warps, 64x32 warp tiles),
// XOR-swizzled SMEM, 3-stage cp.async ring, 1 sync/stage, 2 CTAs/SM.
// R13: strength-reduced addressing — strided loader (per-thread chunk/row&7
// invariant) and XOR-folded LDSM addresses (swz(row,cB+cs)=swz(row,cs)^(cB<<4)).
// EPI 0: h = fp16(gelu(.+b)); EPI 1: yh = fp16(g*(.+b))
// ---------------------------------------------------------------------------
#define STAGEB 32768                     // A(16K) + B(16K) per stage
#define NSTAGE 3
#define SM_BYTES (NSTAGE * STAGEB)       // 98304 -> 2 CTAs/SM

__device__ __forceinline__ u32 swz(u32 row, u32 ch) {   // byte offset, 128B rows
    return row * 128 + ((ch ^ (row & 7)) << 4);
}

template <int EPI>
__global__ void __launch_bounds__(256, 2) mma_gemm(
    const u16* __restrict__ Ah, size_t aStride,
    const u16* __restrict__ Bh,
    const float* __restrict__ bias,
    const float* __restrict__ gate,
    u16* __restrict__ Ch,
    size_t cStride, int K)
{
    extern __shared__ char sm[];
    const u32 sb = smem_u32(sm);

    const int tid  = threadIdx.x;
    const int wid  = tid >> 5;
    const int lane = tid & 31;
    const int wm   = wid & 1;       // 2 warps in M, 64 rows each
    const int wn   = wid >> 1;      // 4 warps in N, 32 cols each
    const int m0   = blockIdx.y * 128;
    const int n0   = blockIdx.x * 128;
    const int e    = blockIdx.z;
    const int N    = gridDim.x * 128;

    const u16* srcA = Ah + (size_t)e * aStride + (size_t)m0 * K;
    const u16* srcB = Bh + (size_t)e * HID * INTER + (size_t)n0 * K;
    bias += (size_t)e * N;

    // ---- loader precompute: chunk c and row&7 invariant across the 8 cp16s
    const u32 lc   = (u32)tid & 7;        // chunk 0..7 (= 8 halves)
    const u32 lr0  = (u32)tid >> 3;       // base row 0..31
    const u32 ldst = swz(lr0, lc);        // dst offset; +4096 per row step of 32
    const u16* lpA = srcA + (size_t)lr0 * K + lc * 8;
    const u16* lpB = srcB + (size_t)lr0 * K + lc * 8;

    // ---- fragment base addresses (XOR-folded swizzle)
    const u32 a_r  = lane & 15;
    const u32 a_cs = lane >> 4;
    const u32 b_r  = (lane & 7) + (((u32)lane >> 4) & 1) * 8;
    const u32 b_cs = ((u32)lane >> 3) & 1;

    u32 abase[4], bbase[2];
#pragma unroll
    for (int mf = 0; mf < 4; mf++)
        abase[mf] = swz((u32)(wm * 64 + mf * 16) + a_r, a_cs);
    bbase[0] = swz((u32)(wn * 32) + b_r, b_cs) + 16384;
    bbase[1] = swz((u32)(wn * 32 + 16) + b_r, b_cs) + 16384;

    float acc[4][4][4];
#pragma unroll
    for (int i = 0; i < 4; i++)
#pragma unroll
        for (int j = 0; j < 4; j++)
#pragma unroll
            for (int q = 0; q < 4; q++) acc[i][j][q] = 0.f;

    const int nst = K / 64;

    // stage loader: strided, 8 cp16 per thread (4 A rows + 4 B rows)
    auto load_stage = [&](int buf, int k0) {
        u32 d = sb + (u32)buf * STAGEB + ldst;
        const u16* pa = lpA + k0;
        const u16* pb = lpB + k0;
#pragma unroll
        for (int i = 0; i < 4; i++)
            cp16(d + (u32)i * 4096, pa + (size_t)i * 32 * K);
#pragma unroll
        for (int i = 0; i < 4; i++)
            cp16(d + 16384 + (u32)i * 4096, pb + (size_t)i * 32 * K);
        asm volatile("cp.async.commit_group;" ::: "memory");
    };

    load_stage(0, 0);
    load_stage(1, 64);

    int buf = 0;
    for (int s = 0; s < nst; s++) {
        if (s + 1 < nst) asm volatile("cp.async.wait_group 1;" ::: "memory");
        else             asm volatile("cp.async.wait_group 0;" ::: "memory");
        __syncthreads();
        if (s + 2 < nst) load_stage((s + 2) % NSTAGE, (s + 2) * 64);

        const u32 base = sb + (u32)buf * STAGEB;

#pragma unroll
        for (int ks = 0; ks < 4; ks++) {            // 4 x k16 per stage
            const u32 kx = (u32)ks * 32;            // (cB=2*ks) << 4
            u32 af[4][4];
#pragma unroll
            for (int mf = 0; mf < 4; mf++)
                ldm_x4(af[mf][0], af[mf][1], af[mf][2], af[mf][3],
                       base + (abase[mf] ^ kx));
            u32 bf[4][2];
            ldm_x4(bf[0][0], bf[0][1], bf[1][0], bf[1][1],
                   base + (bbase[0] ^ kx));
            ldm_x4(bf[2][0], bf[2][1], bf[3][0], bf[3][1],
                   base + (bbase[1] ^ kx));
#pragma unroll
            for (int mf = 0; mf < 4; mf++)
#pragma unroll
                for (int nf = 0; nf < 4; nf++)
                    mma_f16(acc[mf][nf], af[mf], bf[nf]);
        }
        buf = (buf + 1 == NSTAGE) ? 0 : buf + 1;
    }

    // ---- epilogue ----
    u16* ChE = Ch + (size_t)e * cStride;

    const int gr = lane >> 2;
    const int tg = lane & 3;
#pragma unroll
    for (int mf = 0; mf < 4; mf++) {
#pragma unroll
        for (int half = 0; half < 2; half++) {
            int r = m0 + wm * 64 + mf * 16 + gr + half * 8;
            float gv = 0.f;
            if (EPI == 1) gv = gate[r * NEXP + e];
#pragma unroll
            for (int nf = 0; nf < 4; nf++) {
                int c = n0 + wn * 32 + nf * 8 + tg * 2;
                float v0 = acc[mf][nf][half * 2 + 0] + bias[c];
                float v1 = acc[mf][nf][half * 2 + 1] + bias[c + 1];
                __half h0, h1;
                if (EPI == 0) {
                    h0 = __float2half_rn(gelu_exact(v0));
                    h1 = __float2half_rn(gelu_exact(v1));
                } else {
                    h0 = __float2half_rn(gv * v0);
                    h1 = __float2half_rn(gv * v1);
                }
                *reinterpret_cast<u32*>(ChE + (size_t)r * N + c) =
                    (u32)__half_as_ushort(h0) |
                    ((u32)__half_as_ushort(h1) << 16);
            }
        }
    }
}

// ---------------------------------------------------------------------------
extern "C" void kernel_launch(void* const* d_in, const int* in_sizes, int n_in,
                              void* d_out, int out_size) {
    const float* x  = (const float*)d_in[0];
    const float* Wg = (const float*)d_in[1];
    const float* W1 = (const float*)d_in[2];
    const float* b1 = (const float*)d_in[3];
    const float* W2 = (const float*)d_in[4];
    const float* b2 = (const float*)d_in[5];
    float* out = (float*)d_out;

    u16 *xh, *w1h, *w2h, *hh, *yh;
    float *gbuf;
    cudaGetSymbolAddress((void**)&xh, g_xh);
    cudaGetSymbolAddress((void**)&w1h, g_w1h);
    cudaGetSymbolAddress((void**)&w2h, g_w2h);
    cudaGetSymbolAddress((void**)&hh, g_hh);
    cudaGetSymbolAddress((void**)&yh, g_yh);
    cudaGetSymbolAddress((void**)&gbuf, g_gate);

    cudaFuncSetAttribute(mma_gemm<0>, cudaFuncAttributeMaxDynamicSharedMemorySize, SM_BYTES);
    cudaFuncSetAttribute(mma_gemm<1>, cudaFuncAttributeMaxDynamicSharedMemorySize, SM_BYTES);

    gate_kernel<<<T_TOK / 8, 256>>>(x, Wg, gbuf);

    size_t n4x = (size_t)T_TOK * HID / 4;
    xcvt_kernel<<<(unsigned)((n4x + 255) / 256), 256>>>(x, xh, n4x);
    tcvt2_kernel<<<32768, dim3(32, 8)>>>(W1, W2, w1h, w2h);

    // GEMM1 all experts: M=T, N=INTER, K=HID
    mma_gemm<0><<<dim3(INTER / 128, T_TOK / 128, NEXP), 256, SM_BYTES>>>(
        xh, 0, w1h, b1, nullptr, hh, (size_t)T_TOK * INTER, HID);

    // GEMM2 all experts: M=T, N=HID, K=INTER (gate folded into epilogue)
    mma_gemm<1><<<dim3(HID / 128, T_TOK / 128, NEXP), 256, SM_BYTES>>>(
        hh, (size_t)T_TOK * INTER, w2h, b2, gbuf, yh,
        (size_t)T_TOK * HID, INTER);

    // out = sum_e yh[e]
    size_t n8o = (size_t)T_TOK * HID / 8;
    reduce_kernel<<<(unsigned)((n8o + 255) / 256), 256>>>(yh, out);
}

// round 17
// speedup vs baseline: 1.1565x; 1.1565x over previous
#include <cuda_runtime.h>
#include <cuda_fp16.h>
#include <cstdint>

#define T_TOK 4096
#define HID   1024
#define INTER 4096
#define NEXP  8

typedef unsigned short u16;
typedef unsigned int   u32;
typedef unsigned long long u64;

// ---------------------------------------------------------------------------
// Device scratch (fp16 operands)
// ---------------------------------------------------------------------------
__device__ u16 g_xh[(size_t)T_TOK * HID];            // fp16 x [T][H]
__device__ u16 g_w1h[(size_t)NEXP * HID * INTER];    // [E][I][H] transposed fp16
__device__ u16 g_w2h[(size_t)NEXP * HID * INTER];    // [E][H][I] transposed fp16
__device__ u16 g_hh[(size_t)NEXP * T_TOK * INTER];   // per-expert h fp16
__device__ u16 g_yh[(size_t)NEXP * T_TOK * HID];     // per-expert gate-weighted y fp16
__device__ float g_gate[T_TOK * NEXP];

// ---------------------------------------------------------------------------
// Helpers
// ---------------------------------------------------------------------------
__device__ __forceinline__ u32 smem_u32(const void* p) {
    u32 a;
    asm("{ .reg .u64 t; cvta.to.shared.u64 t, %1; cvt.u32.u64 %0, t; }"
        : "=r"(a) : "l"(p));
    return a;
}
__device__ __forceinline__ void cp16(u32 dst, const void* src) {
    asm volatile("cp.async.cg.shared.global [%0], [%1], 16;"
                 :: "r"(dst), "l"(src));
}
__device__ __forceinline__ void ldm_x4(u32& r0, u32& r1, u32& r2, u32& r3, u32 a) {
    asm volatile("ldmatrix.sync.aligned.m8n8.x4.shared.b16 {%0,%1,%2,%3}, [%4];"
                 : "=r"(r0), "=r"(r1), "=r"(r2), "=r"(r3) : "r"(a));
}
__device__ __forceinline__ void mma_f16(float* c, const u32* a, const u32* b) {
    asm volatile("mma.sync.aligned.m16n8k16.row.col.f32.f16.f16.f32 "
                 "{%0,%1,%2,%3}, {%4,%5,%6,%7}, {%8,%9}, {%0,%1,%2,%3};"
                 : "+f"(c[0]), "+f"(c[1]), "+f"(c[2]), "+f"(c[3])
                 : "r"(a[0]), "r"(a[1]), "r"(a[2]), "r"(a[3]),
                   "r"(b[0]), "r"(b[1]));
}
// Fast GELU: tanh formulation + HW MUFU tanh. Pre-activations are N(0,0.33),
// where |gelu_tanh - gelu_erf| < 1e-4; MUFU adds <=6e-4*|v|/2 abs. Combined
// contribution to output rel_err ~3e-4 (quadrature w/ 4.5e-4 -> ~5.4e-4 < 1e-3).
__device__ __forceinline__ float gelu_fast(float v) {
    float c = 0.79788456f * v * fmaf(0.044715f * v, v, 1.0f);
    float t;
    asm("tanh.approx.f32 %0, %1;" : "=f"(t) : "f"(c));
    float vh = 0.5f * v;
    return fmaf(vh, t, vh);
}

// ---------------------------------------------------------------------------
// Fused prepass: one launch, flattened grid, 256 threads/block.
//   blocks [0, 32768)        : W1/W2 transpose+cvt (64x32 tiles)
//   blocks [32768, 36864)    : x fp32 -> fp16
//   blocks [36864, 37376)    : gate softmax (8 tokens/block, 1 warp/token)
// ---------------------------------------------------------------------------
__global__ void prep_kernel(const float* __restrict__ x,
                            const float* __restrict__ Wg,
                            const float* __restrict__ W1,
                            const float* __restrict__ W2,
                            u16* __restrict__ xh,
                            u16* __restrict__ o1, u16* __restrict__ o2,
                            float* __restrict__ gate) {
    int b = blockIdx.x;
    int tid = threadIdx.x;

    if (b < 32768) {
        // ---- weight transpose + cvt ----
        __shared__ float t[64][33];
        const float* Win; u16* oT; int R, C, c0, r0;
        if (b < 16384) {              // W1: R=1024, C=4096; 128x16 tiles/expert
            int e = b >> 11, tt = b & 2047;
            R = HID; C = INTER;
            c0 = (tt & 127) * 32; r0 = (tt >> 7) * 64;
            Win = W1 + (size_t)e * R * C;
            oT  = o1 + (size_t)e * R * C;
        } else {                      // W2: R=4096, C=1024; 32x64 tiles/expert
            int bb = b - 16384;
            int e = bb >> 11, tt = bb & 2047;
            R = INTER; C = HID;
            c0 = (tt & 31) * 32; r0 = (tt >> 5) * 64;
            Win = W2 + (size_t)e * R * C;
            oT  = o2 + (size_t)e * R * C;
        }
        int tx = tid & 31, ty = tid >> 5;  // (32, 8)
#pragma unroll
        for (int i = 0; i < 8; i++)
            t[ty + i * 8][tx] = Win[(size_t)(r0 + ty + i * 8) * C + c0 + tx];
        __syncthreads();
#pragma unroll
        for (int i = 0; i < 4; i++) {
            int crow = ty + i * 8;
            __half h0 = __float2half_rn(t[2 * tx + 0][crow]);
            __half h1 = __float2half_rn(t[2 * tx + 1][crow]);
            size_t off = (size_t)(c0 + crow) * R + r0 + 2 * tx;
            *reinterpret_cast<u32*>(oT + off) =
                (u32)__half_as_ushort(h0) | ((u32)__half_as_ushort(h1) << 16);
        }
    } else if (b < 36864) {
        // ---- x convert ----
        size_t i = (size_t)(b - 32768) * 256 + tid;   // over T*H/4
        float4 v = reinterpret_cast<const float4*>(x)[i];
        __half h[4];
        h[0] = __float2half_rn(v.x); h[1] = __float2half_rn(v.y);
        h[2] = __float2half_rn(v.z); h[3] = __float2half_rn(v.w);
        reinterpret_cast<u64*>(xh)[i] = *reinterpret_cast<u64*>(h);
    } else {
        // ---- gate softmax ----
        int warp = (b - 36864) * 8 + (tid >> 5);
        int lane = tid & 31;
        const float* xr = x + (size_t)warp * HID;
        float acc[NEXP];
#pragma unroll
        for (int e = 0; e < NEXP; e++) acc[e] = 0.f;
        for (int k = lane; k < HID; k += 32) {
            float xv = xr[k];
#pragma unroll
            for (int e = 0; e < NEXP; e++)
                acc[e] = fmaf(xv, Wg[e * HID + k], acc[e]);
        }
#pragma unroll
        for (int e = 0; e < NEXP; e++)
#pragma unroll
            for (int off = 16; off > 0; off >>= 1)
                acc[e] += __shfl_xor_sync(0xffffffffu, acc[e], off);
        if (lane == 0) {
            float mx = acc[0];
#pragma unroll
            for (int e = 1; e < NEXP; e++) mx = fmaxf(mx, acc[e]);
            float s = 0.f;
#pragma unroll
            for (int e = 0; e < NEXP; e++) { acc[e] = expf(acc[e] - mx); s += acc[e]; }
            float inv = 1.f / s;
#pragma unroll
            for (int e = 0; e < NEXP; e++) gate[warp * NEXP + e] = acc[e] * inv;
        }
    }
}

// ---------------------------------------------------------------------------
// Final reduce: out[t,h] = sum_e yh[e,t,h]  (gate already folded in)
// ---------------------------------------------------------------------------
__global__ void reduce_kernel(const u16* __restrict__ yh,
                              float* __restrict__ out) {
    size_t idx = (size_t)blockIdx.x * blockDim.x + threadIdx.x;  // over T*H/8
    if (idx >= (size_t)T_TOK * HID / 8) return;
    float s[8] = {0.f, 0.f, 0.f, 0.f, 0.f, 0.f, 0.f, 0.f};
#pragma unroll
    for (int e = 0; e < NEXP; e++) {
        uint4 v = reinterpret_cast<const uint4*>(
            yh + (size_t)e * T_TOK * HID)[idx];
        const u32 w[4] = {v.x, v.y, v.z, v.w};
#pragma unroll
        for (int q = 0; q < 4; q++) {
            float2 f = __half22float2(*reinterpret_cast<const __half2*>(&w[q]));
            s[q * 2 + 0] += f.x;
            s[q * 2 + 1] += f.y;
        }
    }
#pragma unroll
    for (int q = 0; q < 2; q++) {
        float4 o = make_float4(s[q * 4 + 0], s[q * 4 + 1],
                               s[q * 4 + 2], s[q * 4 + 3]);
        reinterpret_cast<float4*>(out)[idx * 2 + q] = o;
    }
}

// ---------------------------------------------------------------------------
// FP16 mma.sync GEMM over grid.z experts: C = A[M,K] @ B[N,K]^T (fp32 accum)
// 128x128 CTA tile, BK=64 halves, 256 threads (8 warps, 64x32 warp tiles),
// XOR-swizzled SMEM, 3-stage cp.async ring, 1 sync/stage, 2 CTAs/SM.
// EPI 0: h = fp16(gelu_fast(.+b)); EPI 1: yh = fp16(g*(.+b))
// ---------------------------------------------------------------------------
#define STAGEB 32768                     // A(16K) + B(16K) per stage
#define NSTAGE 3
#define SM_BYTES (NSTAGE * STAGEB)       // 98304 -> 2 CTAs/SM

__device__ __forceinline__ u32 swz(u32 row, u32 ch) {   // byte offset, 128B rows
    return row * 128 + ((ch ^ (row & 7)) << 4);
}

template <int EPI>
__global__ void __launch_bounds__(256, 2) mma_gemm(
    const u16* __restrict__ Ah, size_t aStride,
    const u16* __restrict__ Bh,
    const float* __restrict__ bias,
    const float* __restrict__ gate,
    u16* __restrict__ Ch,
    size_t cStride, int K)
{
    extern __shared__ char sm[];
    const u32 sb = smem_u32(sm);

    const int tid  = threadIdx.x;
    const int wid  = tid >> 5;
    const int lane = tid & 31;
    const int wm   = wid & 1;       // 2 warps in M, 64 rows each
    const int wn   = wid >> 1;      // 4 warps in N, 32 cols each
    const int m0   = blockIdx.y * 128;
    const int n0   = blockIdx.x * 128;
    const int e    = blockIdx.z;
    const int N    = gridDim.x * 128;

    const u16* srcA = Ah + (size_t)e * aStride + (size_t)m0 * K;
    const u16* srcB = Bh + (size_t)e * HID * INTER + (size_t)n0 * K;
    bias += (size_t)e * N;

    // ---- loader precompute: chunk c and row&7 invariant across the 8 cp16s
    const u32 lc   = (u32)tid & 7;        // chunk 0..7 (= 8 halves)
    const u32 lr0  = (u32)tid >> 3;       // base row 0..31
    const u32 ldst = swz(lr0, lc);        // dst offset; +4096 per row step of 32
    const u16* lpA = srcA + (size_t)lr0 * K + lc * 8;
    const u16* lpB = srcB + (size_t)lr0 * K + lc * 8;

    // ---- fragment base addresses (XOR-folded swizzle)
    const u32 a_r  = lane & 15;
    const u32 a_cs = lane >> 4;
    const u32 b_r  = (lane & 7) + (((u32)lane >> 4) & 1) * 8;
    const u32 b_cs = ((u32)lane >> 3) & 1;

    u32 abase[4], bbase[2];
#pragma unroll
    for (int mf = 0; mf < 4; mf++)
        abase[mf] = swz((u32)(wm * 64 + mf * 16) + a_r, a_cs);
    bbase[0] = swz((u32)(wn * 32) + b_r, b_cs) + 16384;
    bbase[1] = swz((u32)(wn * 32 + 16) + b_r, b_cs) + 16384;

    float acc[4][4][4];
#pragma unroll
    for (int i = 0; i < 4; i++)
#pragma unroll
        for (int j = 0; j < 4; j++)
#pragma unroll
            for (int q = 0; q < 4; q++) acc[i][j][q] = 0.f;

    const int nst = K / 64;

    // stage loader: strided, 8 cp16 per thread (4 A rows + 4 B rows)
    auto load_stage = [&](int buf, int k0) {
        u32 d = sb + (u32)buf * STAGEB + ldst;
        const u16* pa = lpA + k0;
        const u16* pb = lpB + k0;
#pragma unroll
        for (int i = 0; i < 4; i++)
            cp16(d + (u32)i * 4096, pa + (size_t)i * 32 * K);
#pragma unroll
        for (int i = 0; i < 4; i++)
            cp16(d + 16384 + (u32)i * 4096, pb + (size_t)i * 32 * K);
        asm volatile("cp.async.commit_group;" ::: "memory");
    };

    load_stage(0, 0);
    load_stage(1, 64);

    int buf = 0;
    for (int s = 0; s < nst; s++) {
        if (s + 1 < nst) asm volatile("cp.async.wait_group 1;" ::: "memory");
        else             asm volatile("cp.async.wait_group 0;" ::: "memory");
        __syncthreads();
        if (s + 2 < nst) load_stage((s + 2) % NSTAGE, (s + 2) * 64);

        const u32 base = sb + (u32)buf * STAGEB;

#pragma unroll
        for (int ks = 0; ks < 4; ks++) {            // 4 x k16 per stage
            const u32 kx = (u32)ks * 32;            // (cB=2*ks) << 4
            u32 af[4][4];
#pragma unroll
            for (int mf = 0; mf < 4; mf++)
                ldm_x4(af[mf][0], af[mf][1], af[mf][2], af[mf][3],
                       base + (abase[mf] ^ kx));
            u32 bf[4][2];
            ldm_x4(bf[0][0], bf[0][1], bf[1][0], bf[1][1],
                   base + (bbase[0] ^ kx));
            ldm_x4(bf[2][0], bf[2][1], bf[3][0], bf[3][1],
                   base + (bbase[1] ^ kx));
#pragma unroll
            for (int mf = 0; mf < 4; mf++)
#pragma unroll
                for (int nf = 0; nf < 4; nf++)
                    mma_f16(acc[mf][nf], af[mf], bf[nf]);
        }
        buf = (buf + 1 == NSTAGE) ? 0 : buf + 1;
    }

    // ---- epilogue ----
    u16* ChE = Ch + (size_t)e * cStride;

    const int gr = lane >> 2;
    const int tg = lane & 3;
#pragma unroll
    for (int mf = 0; mf < 4; mf++) {
#pragma unroll
        for (int half = 0; half < 2; half++) {
            int r = m0 + wm * 64 + mf * 16 + gr + half * 8;
            float gv = 0.f;
            if (EPI == 1) gv = gate[r * NEXP + e];
#pragma unroll
            for (int nf = 0; nf < 4; nf++) {
                int c = n0 + wn * 32 + nf * 8 + tg * 2;
                float v0 = acc[mf][nf][half * 2 + 0] + bias[c];
                float v1 = acc[mf][nf][half * 2 + 1] + bias[c + 1];
                __half h0, h1;
                if (EPI == 0) {
                    h0 = __float2half_rn(gelu_fast(v0));
                    h1 = __float2half_rn(gelu_fast(v1));
                } else {
                    h0 = __float2half_rn(gv * v0);
                    h1 = __float2half_rn(gv * v1);
                }
                *reinterpret_cast<u32*>(ChE + (size_t)r * N + c) =
                    (u32)__half_as_ushort(h0) |
                    ((u32)__half_as_ushort(h1) << 16);
            }
        }
    }
}

// ---------------------------------------------------------------------------
extern "C" void kernel_launch(void* const* d_in, const int* in_sizes, int n_in,
                              void* d_out, int out_size) {
    const float* x  = (const float*)d_in[0];
    const float* Wg = (const float*)d_in[1];
    const float* W1 = (const float*)d_in[2];
    const float* b1 = (const float*)d_in[3];
    const float* W2 = (const float*)d_in[4];
    const float* b2 = (const float*)d_in[5];
    float* out = (float*)d_out;

    u16 *xh, *w1h, *w2h, *hh, *yh;
    float *gbuf;
    cudaGetSymbolAddress((void**)&xh, g_xh);
    cudaGetSymbolAddress((void**)&w1h, g_w1h);
    cudaGetSymbolAddress((void**)&w2h, g_w2h);
    cudaGetSymbolAddress((void**)&hh, g_hh);
    cudaGetSymbolAddress((void**)&yh, g_yh);
    cudaGetSymbolAddress((void**)&gbuf, g_gate);

    cudaFuncSetAttribute(mma_gemm<0>, cudaFuncAttributeMaxDynamicSharedMemorySize, SM_BYTES);
    cudaFuncSetAttribute(mma_gemm<1>, cudaFuncAttributeMaxDynamicSharedMemorySize, SM_BYTES);

    // Fused prepass: weight transpose+cvt, x cvt, gate softmax (one launch)
    prep_kernel<<<37376, 256>>>(x, Wg, W1, W2, xh, w1h, w2h, gbuf);

    // GEMM1 all experts: M=T, N=INTER, K=HID
    mma_gemm<0><<<dim3(INTER / 128, T_TOK / 128, NEXP), 256, SM_BYTES>>>(
        xh, 0, w1h, b1, nullptr, hh, (size_t)T_TOK * INTER, HID);

    // GEMM2 all experts: M=T, N=HID, K=INTER (gate folded into epilogue)
    mma_gemm<1><<<dim3(HID / 128, T_TOK / 128, NEXP), 256, SM_BYTES>>>(
        hh, (size_t)T_TOK * INTER, w2h, b2, gbuf, yh,
        (size_t)T_TOK * HID, INTER);

    // out = sum_e yh[e]
    size_t n8o = (size_t)T_TOK * HID / 8;
    reduce_kernel<<<(unsigned)((n8o + 255) / 256), 256>>>(yh, out);
}